// round 15
// baseline (speedup 1.0000x reference)
#include <cuda_runtime.h>
#include <cuda_fp16.h>
#include <math_constants.h>
#include <cstdint>
#include <cstring>

#define N_NODES 10000
#define N_EDGES 320000
#define IN_F    512
#define OUT_F   256
#define ALPHA   0.2f

// ---------------- scratch (device globals; no allocation allowed) ----------
__device__ __half g_h16[(size_t)N_NODES * OUT_F];
__device__ float g_s1[N_NODES];
__device__ float g_s2[N_NODES];
__device__ int   g_rowptr[N_NODES + 1];
__device__ int   g_cnt[N_NODES];
__device__ int   g_col[N_EDGES];
__device__ int   g_pos[N_EDGES];
__device__ int   g_is64;
__device__ __half g_w16[(size_t)OUT_F * IN_F];

// ---------------- small helpers --------------------------------------------
__device__ __forceinline__ uint32_t h2_bits(__half2 h) {
    uint32_t u;
    memcpy(&u, &h, 4);
    return u;
}
__device__ __forceinline__ void ldsm4(uint32_t* r, uint32_t addr) {
    asm volatile("ldmatrix.sync.aligned.m8n8.x4.shared.b16 {%0,%1,%2,%3}, [%4];"
                 : "=r"(r[0]), "=r"(r[1]), "=r"(r[2]), "=r"(r[3]) : "r"(addr));
}
__device__ __forceinline__ void mma16816(float* c, const uint32_t* A, uint32_t b0, uint32_t b1) {
    asm volatile("mma.sync.aligned.m16n8k16.row.col.f32.f16.f16.f32 "
                 "{%0,%1,%2,%3}, {%4,%5,%6,%7}, {%8,%9}, {%0,%1,%2,%3};"
                 : "+f"(c[0]), "+f"(c[1]), "+f"(c[2]), "+f"(c[3])
                 : "r"(A[0]), "r"(A[1]), "r"(A[2]), "r"(A[3]), "r"(b0), "r"(b1));
}
__device__ __forceinline__ void cpa16(uint32_t dst, const void* src) {
    asm volatile("cp.async.cg.shared.global [%0], [%1], 16;" :: "r"(dst), "l"(src));
}
__device__ __forceinline__ int clampN(int v) {
    return (v < 0) ? 0 : (v >= N_NODES ? N_NODES - 1 : v);
}
__device__ __forceinline__ void edge4(const void* el, int boff, int* s) {
    if (g_is64) {
        longlong2 p0 = ((const longlong2*)el)[boff >> 1];
        longlong2 p1 = ((const longlong2*)el)[(boff >> 1) + 1];
        s[0] = clampN((int)p0.x); s[1] = clampN((int)p0.y);
        s[2] = clampN((int)p1.x); s[3] = clampN((int)p1.y);
    } else {
        int4 p = ((const int4*)el)[boff >> 2];
        s[0] = clampN(p.x); s[1] = clampN(p.y);
        s[2] = clampN(p.z); s[3] = clampN(p.w);
    }
}

// ---------------- W fp32 -> fp16 (tiny; runs on side stream) ---------------
__global__ void wcvt_kernel(const float* __restrict__ W) {
    int i = blockIdx.x * blockDim.x + threadIdx.x;     // 8 floats per thread
    if (i >= OUT_F * IN_F / 8) return;
    float4 v0 = ((const float4*)W)[2 * i];
    float4 v1 = ((const float4*)W)[2 * i + 1];
    __half2 H0 = {__float2half_rn(v0.x), __float2half_rn(v0.y)};
    __half2 H1 = {__float2half_rn(v0.z), __float2half_rn(v0.w)};
    __half2 H2 = {__float2half_rn(v1.x), __float2half_rn(v1.y)};
    __half2 H3 = {__float2half_rn(v1.z), __float2half_rn(v1.w)};
    ((__half2*)g_w16)[4 * i]     = H0;
    ((__half2*)g_w16)[4 * i + 1] = H1;
    ((__half2*)g_w16)[4 * i + 2] = H2;
    ((__half2*)g_w16)[4 * i + 3] = H3;
}

// ---------------- init (+ dtype probe in block 0) ---------------------------
__global__ void init_kernel(const int* __restrict__ p) {
    int i = blockIdx.x * blockDim.x + threadIdx.x;
    if (i == 0) {
        int nz = 0;
#pragma unroll
        for (int j = 0; j < 64; j++) nz |= p[2 * j + 1];
        g_is64 = (nz == 0) ? 1 : 0;
    }
    if (i < N_NODES) { g_cnt[i] = 0; g_s1[i] = 0.f; g_s2[i] = 0.f; }
}

// ---------------- tensor-core GEMM, fused X fp32->fp16, reg-pipelined ------
#define BM 128
#define BN 128
#define KB 32
#define KST 40
#define STG_B (BM * KST * 2)        // 10240 bytes per stage per array
#define NC (IN_F / KB)              // 16
#define SM_GEMM (4 * STG_B)         // A0,A1,B0,B1 = 40960

__global__ void __launch_bounds__(256, 2) gemm_mma_kernel(
    const float* __restrict__ X,
    const float* __restrict__ bias, const float* __restrict__ av)
{
    extern __shared__ char dsm[];
    const uint32_t smb = (uint32_t)__cvta_generic_to_shared(dsm);

    const int tid  = threadIdx.x;
    const int lane = tid & 31;
    const int wid  = tid >> 5;
    const int wm   = wid & 3;
    const int wn   = wid >> 2;
    const int bm   = blockIdx.x * BM;
    const int bn   = blockIdx.y * BN;

    float acc[2][8][4];
#pragma unroll
    for (int i = 0; i < 2; i++)
#pragma unroll
        for (int j = 0; j < 8; j++)
#pragma unroll
            for (int q = 0; q < 4; q++) acc[i][j][q] = 0.f;

    const int sr = tid >> 1;
    const int sh = (tid & 1) * 16;
    const int rowA = (bm + sr < N_NODES) ? bm + sr : N_NODES - 1;
    const float*  xp = X + (size_t)rowA * IN_F + sh;
    const __half* wp = g_w16 + (size_t)(bn + sr) * IN_F + sh;
    const uint32_t sdst = (uint32_t)(sr * KST + sh) * 2;

    const uint32_t a_row = lane & 15, a_cb = (lane >> 4) * 8;
    const uint32_t b_row = (lane & 7) + ((lane & 16) ? 8 : 0);
    const uint32_t b_cb  = (lane & 8) ? 8 : 0;

    uint32_t xr[8];
#define LOADX(ch) do {                                            \
    const float* _p = xp + (ch) * KB;                             \
    float4 v0 = *(const float4*)(_p);                             \
    float4 v1 = *(const float4*)(_p + 4);                         \
    float4 v2 = *(const float4*)(_p + 8);                         \
    float4 v3 = *(const float4*)(_p + 12);                        \
    xr[0] = h2_bits(__floats2half2_rn(v0.x, v0.y));               \
    xr[1] = h2_bits(__floats2half2_rn(v0.z, v0.w));               \
    xr[2] = h2_bits(__floats2half2_rn(v1.x, v1.y));               \
    xr[3] = h2_bits(__floats2half2_rn(v1.z, v1.w));               \
    xr[4] = h2_bits(__floats2half2_rn(v2.x, v2.y));               \
    xr[5] = h2_bits(__floats2half2_rn(v2.z, v2.w));               \
    xr[6] = h2_bits(__floats2half2_rn(v3.x, v3.y));               \
    xr[7] = h2_bits(__floats2half2_rn(v3.z, v3.w));               \
} while (0)

#define CPW(ch) do {                                              \
    uint32_t _b = smb + 2 * STG_B + ((ch) & 1) * STG_B + sdst;    \
    cpa16(_b,      wp + (ch) * KB);                               \
    cpa16(_b + 16, wp + (ch) * KB + 8);                           \
    asm volatile("cp.async.commit_group;" ::: "memory");          \
} while (0)

    LOADX(0);
    CPW(0);

    for (int ch = 0; ch < NC; ch++) {
        __syncthreads();
        {
            uint32_t _a = smb + (ch & 1) * STG_B + sdst;
            asm volatile("st.shared.v4.b32 [%0], {%1,%2,%3,%4};"
                         :: "r"(_a), "r"(xr[0]), "r"(xr[1]), "r"(xr[2]), "r"(xr[3]));
            asm volatile("st.shared.v4.b32 [%0], {%1,%2,%3,%4};"
                         :: "r"(_a + 16), "r"(xr[4]), "r"(xr[5]), "r"(xr[6]), "r"(xr[7]));
        }
        if (ch + 1 < NC) {
            CPW(ch + 1);
            LOADX(ch + 1);
            asm volatile("cp.async.wait_group 1;" ::: "memory");
        } else {
            asm volatile("cp.async.wait_group 0;" ::: "memory");
        }
        __syncthreads();

        const uint32_t sA_b = smb + (ch & 1) * STG_B;
        const uint32_t sB_b = smb + 2 * STG_B + (ch & 1) * STG_B;

#pragma unroll
        for (int ks = 0; ks < KB; ks += 16) {
            uint32_t ah[2][4];
#pragma unroll
            for (int mi = 0; mi < 2; mi++) {
                uint32_t off = ((wm * 32 + mi * 16 + a_row) * KST + ks + a_cb) * 2;
                ldsm4(ah[mi], sA_b + off);
            }
#pragma unroll
            for (int g = 0; g < 4; g++) {
                uint32_t off = ((wn * 64 + g * 16 + b_row) * KST + ks + b_cb) * 2;
                uint32_t bh[4];
                ldsm4(bh, sB_b + off);
#pragma unroll
                for (int mi = 0; mi < 2; mi++) {
                    mma16816(acc[mi][2 * g],     ah[mi], bh[0], bh[1]);
                    mma16816(acc[mi][2 * g + 1], ah[mi], bh[2], bh[3]);
                }
            }
        }
    }
#undef LOADX
#undef CPW

    const int q  = lane >> 2;
    const int qt = lane & 3;
#pragma unroll
    for (int mi = 0; mi < 2; mi++) {
#pragma unroll
        for (int half = 0; half < 2; half++) {
            int row = bm + wm * 32 + mi * 16 + half * 8 + q;
            bool vr = (row < N_NODES);
            float p1 = 0.f, p2 = 0.f;
#pragma unroll
            for (int ni = 0; ni < 8; ni++) {
                int col = bn + wn * 64 + ni * 8 + qt * 2;
                float v0 = acc[mi][ni][half * 2 + 0] + bias[col];
                float v1 = acc[mi][ni][half * 2 + 1] + bias[col + 1];
                if (vr) {
                    __half2 hh = __floats2half2_rn(v0, v1);
                    *(__half2*)(g_h16 + (size_t)row * OUT_F + col) = hh;
                }
                p1 += v0 * av[col]         + v1 * av[col + 1];
                p2 += v0 * av[OUT_F + col] + v1 * av[OUT_F + col + 1];
            }
            p1 += __shfl_xor_sync(0xffffffffu, p1, 1);
            p1 += __shfl_xor_sync(0xffffffffu, p1, 2);
            p2 += __shfl_xor_sync(0xffffffffu, p2, 1);
            p2 += __shfl_xor_sync(0xffffffffu, p2, 2);
            if (qt == 0 && vr) {
                atomicAdd(&g_s1[row], p1);
                atomicAdd(&g_s2[row], p2);
            }
        }
    }
}

// ---------------- CSR build ------------------------------------------------
// count: also records each edge's within-row rank (atomic return value),
// so fill needs NO atomics.
__global__ void count_kernel(const void* __restrict__ el) {
    int e0 = (blockIdx.x * blockDim.x + threadIdx.x) * 4;
    if (e0 >= N_EDGES) return;
    int s[4];
    edge4(el, e0, s);
#pragma unroll
    for (int u = 0; u < 4; u++)
        g_pos[e0 + u] = atomicAdd(&g_cnt[s[u]], 1);
}

// warp-shuffle scan: 2 barriers total (vs 20 in Hillis-Steele version)
__global__ void scan_kernel() {
    __shared__ int warpsum[32];
    const int t    = threadIdx.x;        // 0..1023
    const int lane = t & 31;
    const int wrp  = t >> 5;
    const int CH   = (N_NODES + 1023) / 1024;   // 10
    const int base = t * CH;

    int s = 0;
    int local[10];
#pragma unroll
    for (int i = 0; i < 10; i++) {
        int idx = base + i;
        int c = (idx < N_NODES) ? g_cnt[idx] : 0;
        local[i] = c;
        s += c;
    }
    // inclusive warp scan of per-thread sums
    int inc = s;
#pragma unroll
    for (int o = 1; o < 32; o <<= 1) {
        int v = __shfl_up_sync(0xffffffffu, inc, o);
        if (lane >= o) inc += v;
    }
    if (lane == 31) warpsum[wrp] = inc;
    __syncthreads();
    if (wrp == 0) {
        int w = warpsum[lane];
        int wi = w;
#pragma unroll
        for (int o = 1; o < 32; o <<= 1) {
            int v = __shfl_up_sync(0xffffffffu, wi, o);
            if (lane >= o) wi += v;
        }
        warpsum[lane] = wi - w;   // exclusive warp offset
    }
    __syncthreads();
    int run = warpsum[wrp] + (inc - s);   // exclusive prefix of this thread
#pragma unroll
    for (int i = 0; i < 10; i++) {
        int idx = base + i;
        if (idx < N_NODES) { g_rowptr[idx] = run; run += local[i]; }
    }
    if (t == 1023) g_rowptr[N_NODES] = run;
}

// fill: atomic-free scatter using the rank captured in count
__global__ void fill_kernel(const void* __restrict__ el) {
    int e = blockIdx.x * blockDim.x + threadIdx.x;
    if (e >= N_EDGES) return;
    int s, t;
    if (g_is64) {
        s = clampN((int)((const long long*)el)[e]);
        t = clampN((int)((const long long*)el)[N_EDGES + e]);
    } else {
        s = clampN(((const int*)el)[e]);
        t = clampN(((const int*)el)[N_EDGES + e]);
    }
    int pos = g_rowptr[s] + g_pos[e];
    if (pos < N_EDGES) g_col[pos] = t;
}

// ---------------- per-row: warp-per-row dedup + softmax + aggregation ------
#define MAXK 128
#define RWARPS 4

__global__ void __launch_bounds__(32 * RWARPS) row_kernel(float* __restrict__ out) {
    __shared__ int   scol[RWARPS][MAXK];
    __shared__ float sval[RWARPS][MAXK];
    __shared__ float sw[RWARPS][MAXK];

    const int wr   = threadIdx.x >> 5;
    const int lane = threadIdx.x & 31;
    const int row  = blockIdx.x * RWARPS + wr;
    if (row >= N_NODES) return;

    int beg = g_rowptr[row];
    int k   = g_rowptr[row + 1] - beg;

    float* op = out + (size_t)row * OUT_F + lane * 8;
    if (k == 0) {
        // all-NEG_BIG row: uniform softmax -> column mean (prob ~e^-32; inline)
        float4 a0 = make_float4(0.f, 0.f, 0.f, 0.f);
        float4 a1 = make_float4(0.f, 0.f, 0.f, 0.f);
        for (int r = 0; r < N_NODES; r++) {
            uint4 hv = *(const uint4*)(g_h16 + (size_t)r * OUT_F + lane * 8);
            float2 f0 = __half22float2(*(__half2*)&hv.x);
            float2 f1 = __half22float2(*(__half2*)&hv.y);
            float2 f2 = __half22float2(*(__half2*)&hv.z);
            float2 f3 = __half22float2(*(__half2*)&hv.w);
            a0.x += f0.x; a0.y += f0.y; a0.z += f1.x; a0.w += f1.y;
            a1.x += f2.x; a1.y += f2.y; a1.z += f3.x; a1.w += f3.y;
        }
        const float s = 1.0f / N_NODES;
        *(float4*)op       = make_float4(a0.x * s, a0.y * s, a0.z * s, a0.w * s);
        *(float4*)(op + 4) = make_float4(a1.x * s, a1.y * s, a1.z * s, a1.w * s);
        return;
    }
    if (k > MAXK) k = MAXK;   // 17-sigma guard

    int*   cols = scol[wr];
    float* val  = sval[wr];
    float* wt   = sw[wr];

    const float s1 = g_s1[row];
    for (int t = lane; t < k; t += 32) {
        int c = g_col[beg + t];
        cols[t] = c;
        float sc = s1 + g_s2[c];
        val[t] = sc > 0.f ? sc : ALPHA * sc;
    }
    __syncwarp();

    for (int t = lane; t < k; t += 32) {
        int c = cols[t];
        bool owner = true;
        for (int j = 0; j < t; j++)
            if (cols[j] == c) { owner = false; break; }
        float v;
        if (owner) {
            v = val[t];
            for (int j = t + 1; j < k; j++)
                if (cols[j] == c) v += val[j];
        } else {
            v = -CUDART_INF_F;
        }
        wt[t] = v;
    }
    __syncwarp();

    float m = -CUDART_INF_F;
    for (int t = lane; t < k; t += 32) m = fmaxf(m, wt[t]);
#pragma unroll
    for (int o = 16; o; o >>= 1) m = fmaxf(m, __shfl_xor_sync(0xffffffffu, m, o));

    float z = 0.f;
    for (int t = lane; t < k; t += 32) {
        float e = __expf(wt[t] - m);
        wt[t] = e;
        z += e;
    }
#pragma unroll
    for (int o = 16; o; o >>= 1) z += __shfl_xor_sync(0xffffffffu, z, o);
    float invZ = 1.0f / z;
    __syncwarp();

    float4 a0 = make_float4(0.f, 0.f, 0.f, 0.f);
    float4 a1 = make_float4(0.f, 0.f, 0.f, 0.f);
#pragma unroll 4
    for (int t = 0; t < k; t++) {
        float wv = wt[t];
        uint4 hv = *(const uint4*)(g_h16 + (size_t)cols[t] * OUT_F + lane * 8);
        float2 f0 = __half22float2(*(__half2*)&hv.x);
        float2 f1 = __half22float2(*(__half2*)&hv.y);
        float2 f2 = __half22float2(*(__half2*)&hv.z);
        float2 f3 = __half22float2(*(__half2*)&hv.w);
        a0.x += wv * f0.x; a0.y += wv * f0.y; a0.z += wv * f1.x; a0.w += wv * f1.y;
        a1.x += wv * f2.x; a1.y += wv * f2.y; a1.z += wv * f3.x; a1.w += wv * f3.y;
    }
    *(float4*)op       = make_float4(a0.x * invZ, a0.y * invZ, a0.z * invZ, a0.w * invZ);
    *(float4*)(op + 4) = make_float4(a1.x * invZ, a1.y * invZ, a1.z * invZ, a1.w * invZ);
}

// ---------------- launch ---------------------------------------------------
extern "C" void kernel_launch(void* const* d_in, const int* in_sizes, int n_in,
                              void* d_out, int out_size) {
    const float* x  = (const float*)d_in[0];
    const float* W  = (const float*)d_in[1];
    const float* b  = (const float*)d_in[2];
    const float* a  = (const float*)d_in[3];
    const void*  el = d_in[4];
    float* out = (float*)d_out;

    static cudaStream_t s_side = nullptr;
    static cudaEvent_t  ev_fork = nullptr, ev_init = nullptr, ev_side = nullptr;
    static bool s_init = false;
    if (!s_init) {
        cudaStreamCreateWithFlags(&s_side, cudaStreamNonBlocking);
        cudaEventCreateWithFlags(&ev_fork, cudaEventDisableTiming);
        cudaEventCreateWithFlags(&ev_init, cudaEventDisableTiming);
        cudaEventCreateWithFlags(&ev_side, cudaEventDisableTiming);
        cudaFuncSetAttribute(gemm_mma_kernel,
                             cudaFuncAttributeMaxDynamicSharedMemorySize, SM_GEMM);
        s_init = true;
    }

    cudaEventRecord(ev_fork, 0);
    cudaStreamWaitEvent(s_side, ev_fork, 0);

    // side: wcvt -> init -> count -> scan -> fill (independent of GEMM output)
    wcvt_kernel<<<(OUT_F * IN_F / 8 + 255) / 256, 256, 0, s_side>>>(W);
    init_kernel<<<(N_NODES + 255) / 256, 256, 0, s_side>>>((const int*)el);
    cudaEventRecord(ev_init, s_side);   // covers g_w16 + zeroed s1/s2
    count_kernel<<<(N_EDGES / 4 + 255) / 256, 256, 0, s_side>>>(el);
    scan_kernel<<<1, 1024, 0, s_side>>>();
    fill_kernel<<<(N_EDGES + 255) / 256, 256, 0, s_side>>>(el);
    cudaEventRecord(ev_side, s_side);

    // main: gemm (fused X conversion) -> row
    cudaStreamWaitEvent(0, ev_init, 0);
    dim3 ggrid((N_NODES + BM - 1) / BM, OUT_F / BN);
    gemm_mma_kernel<<<ggrid, 256, SM_GEMM>>>(x, b, a);

    cudaStreamWaitEvent(0, ev_side, 0);
    row_kernel<<<(N_NODES + RWARPS - 1) / RWARPS, 32 * RWARPS>>>(out);
}

// round 16
// speedup vs baseline: 1.0298x; 1.0298x over previous
#include <cuda_runtime.h>
#include <cuda_fp16.h>
#include <math_constants.h>
#include <cstdint>
#include <cstring>

#define N_NODES 10000
#define N_EDGES 320000
#define IN_F    512
#define OUT_F   256
#define ALPHA   0.2f
#define ELLW    96          // ELL row capacity (P(Poisson(32) > 96) < 1e-18)

// ---------------- scratch (device globals; no allocation allowed) ----------
__device__ __half g_h16[(size_t)N_NODES * OUT_F];
__device__ float g_s1[N_NODES];
__device__ float g_s2[N_NODES];
__device__ int   g_cnt[N_NODES];
__device__ int   g_ecol[(size_t)N_NODES * ELLW];
__device__ int   g_is64;
__device__ __half g_w16[(size_t)OUT_F * IN_F];

// ---------------- small helpers --------------------------------------------
__device__ __forceinline__ uint32_t h2_bits(__half2 h) {
    uint32_t u;
    memcpy(&u, &h, 4);
    return u;
}
__device__ __forceinline__ void ldsm4(uint32_t* r, uint32_t addr) {
    asm volatile("ldmatrix.sync.aligned.m8n8.x4.shared.b16 {%0,%1,%2,%3}, [%4];"
                 : "=r"(r[0]), "=r"(r[1]), "=r"(r[2]), "=r"(r[3]) : "r"(addr));
}
__device__ __forceinline__ void mma16816(float* c, const uint32_t* A, uint32_t b0, uint32_t b1) {
    asm volatile("mma.sync.aligned.m16n8k16.row.col.f32.f16.f16.f32 "
                 "{%0,%1,%2,%3}, {%4,%5,%6,%7}, {%8,%9}, {%0,%1,%2,%3};"
                 : "+f"(c[0]), "+f"(c[1]), "+f"(c[2]), "+f"(c[3])
                 : "r"(A[0]), "r"(A[1]), "r"(A[2]), "r"(A[3]), "r"(b0), "r"(b1));
}
__device__ __forceinline__ void cpa16(uint32_t dst, const void* src) {
    asm volatile("cp.async.cg.shared.global [%0], [%1], 16;" :: "r"(dst), "l"(src));
}
__device__ __forceinline__ int clampN(int v) {
    return (v < 0) ? 0 : (v >= N_NODES ? N_NODES - 1 : v);
}

// ---------------- setup: W fp32->fp16 (blocks 0..63) + init (blocks 64..) ---
#define WCVT_BLOCKS 64   // 64 * 256 threads * 8 floats = 131072 = OUT_F*IN_F
__global__ void setup_kernel(const float* __restrict__ W, const int* __restrict__ p) {
    if (blockIdx.x < WCVT_BLOCKS) {
        int i = blockIdx.x * blockDim.x + threadIdx.x;   // 8 floats per thread
        float4 v0 = ((const float4*)W)[2 * i];
        float4 v1 = ((const float4*)W)[2 * i + 1];
        __half2 H0 = {__float2half_rn(v0.x), __float2half_rn(v0.y)};
        __half2 H1 = {__float2half_rn(v0.z), __float2half_rn(v0.w)};
        __half2 H2 = {__float2half_rn(v1.x), __float2half_rn(v1.y)};
        __half2 H3 = {__float2half_rn(v1.z), __float2half_rn(v1.w)};
        ((__half2*)g_w16)[4 * i]     = H0;
        ((__half2*)g_w16)[4 * i + 1] = H1;
        ((__half2*)g_w16)[4 * i + 2] = H2;
        ((__half2*)g_w16)[4 * i + 3] = H3;
    } else {
        int i = (blockIdx.x - WCVT_BLOCKS) * blockDim.x + threadIdx.x;
        if (i == 0) {
            int nz = 0;
#pragma unroll
            for (int j = 0; j < 64; j++) nz |= p[2 * j + 1];
            g_is64 = (nz == 0) ? 1 : 0;
        }
        if (i < N_NODES) { g_cnt[i] = 0; g_s1[i] = 0.f; g_s2[i] = 0.f; }
    }
}

// ---------------- count: direct ELL scatter (no scan, no fill) --------------
__global__ void count_kernel(const void* __restrict__ el) {
    int e0 = (blockIdx.x * blockDim.x + threadIdx.x) * 4;
    if (e0 >= N_EDGES) return;
    int s[4], t[4];
    if (g_is64) {
        const longlong2* sp = (const longlong2*)el;
        const longlong2* tp = (const longlong2*)((const long long*)el + N_EDGES);
        longlong2 s0 = sp[e0 >> 1], s1 = sp[(e0 >> 1) + 1];
        longlong2 t0 = tp[e0 >> 1], t1 = tp[(e0 >> 1) + 1];
        s[0] = clampN((int)s0.x); s[1] = clampN((int)s0.y);
        s[2] = clampN((int)s1.x); s[3] = clampN((int)s1.y);
        t[0] = clampN((int)t0.x); t[1] = clampN((int)t0.y);
        t[2] = clampN((int)t1.x); t[3] = clampN((int)t1.y);
    } else {
        int4 sv = ((const int4*)el)[e0 >> 2];
        int4 tv = ((const int4*)((const int*)el + N_EDGES))[e0 >> 2];
        s[0] = clampN(sv.x); s[1] = clampN(sv.y); s[2] = clampN(sv.z); s[3] = clampN(sv.w);
        t[0] = clampN(tv.x); t[1] = clampN(tv.y); t[2] = clampN(tv.z); t[3] = clampN(tv.w);
    }
#pragma unroll
    for (int u = 0; u < 4; u++) {
        int rank = atomicAdd(&g_cnt[s[u]], 1);
        if (rank < ELLW) g_ecol[s[u] * ELLW + rank] = t[u];
    }
}

// ---------------- tensor-core GEMM, fused X fp32->fp16, reg-pipelined ------
#define BM 128
#define BN 128
#define KB 32
#define KST 40
#define STG_B (BM * KST * 2)        // 10240 bytes per stage per array
#define NC (IN_F / KB)              // 16
#define SM_GEMM (4 * STG_B)         // A0,A1,B0,B1 = 40960

__global__ void __launch_bounds__(256, 2) gemm_mma_kernel(
    const float* __restrict__ X,
    const float* __restrict__ bias, const float* __restrict__ av)
{
    extern __shared__ char dsm[];
    const uint32_t smb = (uint32_t)__cvta_generic_to_shared(dsm);

    const int tid  = threadIdx.x;
    const int lane = tid & 31;
    const int wid  = tid >> 5;
    const int wm   = wid & 3;
    const int wn   = wid >> 2;
    const int bm   = blockIdx.x * BM;
    const int bn   = blockIdx.y * BN;

    float acc[2][8][4];
#pragma unroll
    for (int i = 0; i < 2; i++)
#pragma unroll
        for (int j = 0; j < 8; j++)
#pragma unroll
            for (int q = 0; q < 4; q++) acc[i][j][q] = 0.f;

    const int sr = tid >> 1;
    const int sh = (tid & 1) * 16;
    const int rowA = (bm + sr < N_NODES) ? bm + sr : N_NODES - 1;
    const float*  xp = X + (size_t)rowA * IN_F + sh;
    const __half* wp = g_w16 + (size_t)(bn + sr) * IN_F + sh;
    const uint32_t sdst = (uint32_t)(sr * KST + sh) * 2;

    const uint32_t a_row = lane & 15, a_cb = (lane >> 4) * 8;
    const uint32_t b_row = (lane & 7) + ((lane & 16) ? 8 : 0);
    const uint32_t b_cb  = (lane & 8) ? 8 : 0;

    uint32_t xr[8];
#define LOADX(ch) do {                                            \
    const float* _p = xp + (ch) * KB;                             \
    float4 v0 = *(const float4*)(_p);                             \
    float4 v1 = *(const float4*)(_p + 4);                         \
    float4 v2 = *(const float4*)(_p + 8);                         \
    float4 v3 = *(const float4*)(_p + 12);                        \
    xr[0] = h2_bits(__floats2half2_rn(v0.x, v0.y));               \
    xr[1] = h2_bits(__floats2half2_rn(v0.z, v0.w));               \
    xr[2] = h2_bits(__floats2half2_rn(v1.x, v1.y));               \
    xr[3] = h2_bits(__floats2half2_rn(v1.z, v1.w));               \
    xr[4] = h2_bits(__floats2half2_rn(v2.x, v2.y));               \
    xr[5] = h2_bits(__floats2half2_rn(v2.z, v2.w));               \
    xr[6] = h2_bits(__floats2half2_rn(v3.x, v3.y));               \
    xr[7] = h2_bits(__floats2half2_rn(v3.z, v3.w));               \
} while (0)

#define CPW(ch) do {                                              \
    uint32_t _b = smb + 2 * STG_B + ((ch) & 1) * STG_B + sdst;    \
    cpa16(_b,      wp + (ch) * KB);                               \
    cpa16(_b + 16, wp + (ch) * KB + 8);                           \
    asm volatile("cp.async.commit_group;" ::: "memory");          \
} while (0)

    LOADX(0);
    CPW(0);

    for (int ch = 0; ch < NC; ch++) {
        __syncthreads();
        {
            uint32_t _a = smb + (ch & 1) * STG_B + sdst;
            asm volatile("st.shared.v4.b32 [%0], {%1,%2,%3,%4};"
                         :: "r"(_a), "r"(xr[0]), "r"(xr[1]), "r"(xr[2]), "r"(xr[3]));
            asm volatile("st.shared.v4.b32 [%0], {%1,%2,%3,%4};"
                         :: "r"(_a + 16), "r"(xr[4]), "r"(xr[5]), "r"(xr[6]), "r"(xr[7]));
        }
        if (ch + 1 < NC) {
            CPW(ch + 1);
            LOADX(ch + 1);
            asm volatile("cp.async.wait_group 1;" ::: "memory");
        } else {
            asm volatile("cp.async.wait_group 0;" ::: "memory");
        }
        __syncthreads();

        const uint32_t sA_b = smb + (ch & 1) * STG_B;
        const uint32_t sB_b = smb + 2 * STG_B + (ch & 1) * STG_B;

#pragma unroll
        for (int ks = 0; ks < KB; ks += 16) {
            uint32_t ah[2][4];
#pragma unroll
            for (int mi = 0; mi < 2; mi++) {
                uint32_t off = ((wm * 32 + mi * 16 + a_row) * KST + ks + a_cb) * 2;
                ldsm4(ah[mi], sA_b + off);
            }
#pragma unroll
            for (int g = 0; g < 4; g++) {
                uint32_t off = ((wn * 64 + g * 16 + b_row) * KST + ks + b_cb) * 2;
                uint32_t bh[4];
                ldsm4(bh, sB_b + off);
#pragma unroll
                for (int mi = 0; mi < 2; mi++) {
                    mma16816(acc[mi][2 * g],     ah[mi], bh[0], bh[1]);
                    mma16816(acc[mi][2 * g + 1], ah[mi], bh[2], bh[3]);
                }
            }
        }
    }
#undef LOADX
#undef CPW

    const int q  = lane >> 2;
    const int qt = lane & 3;
#pragma unroll
    for (int mi = 0; mi < 2; mi++) {
#pragma unroll
        for (int half = 0; half < 2; half++) {
            int row = bm + wm * 32 + mi * 16 + half * 8 + q;
            bool vr = (row < N_NODES);
            float p1 = 0.f, p2 = 0.f;
#pragma unroll
            for (int ni = 0; ni < 8; ni++) {
                int col = bn + wn * 64 + ni * 8 + qt * 2;
                float v0 = acc[mi][ni][half * 2 + 0] + bias[col];
                float v1 = acc[mi][ni][half * 2 + 1] + bias[col + 1];
                if (vr) {
                    __half2 hh = __floats2half2_rn(v0, v1);
                    *(__half2*)(g_h16 + (size_t)row * OUT_F + col) = hh;
                }
                p1 += v0 * av[col]         + v1 * av[col + 1];
                p2 += v0 * av[OUT_F + col] + v1 * av[OUT_F + col + 1];
            }
            p1 += __shfl_xor_sync(0xffffffffu, p1, 1);
            p1 += __shfl_xor_sync(0xffffffffu, p1, 2);
            p2 += __shfl_xor_sync(0xffffffffu, p2, 1);
            p2 += __shfl_xor_sync(0xffffffffu, p2, 2);
            if (qt == 0 && vr) {
                atomicAdd(&g_s1[row], p1);
                atomicAdd(&g_s2[row], p2);
            }
        }
    }
}

// ---------------- per-row: warp-per-row dedup + softmax + aggregation ------
#define RWARPS 4

__global__ void __launch_bounds__(32 * RWARPS) row_kernel(float* __restrict__ out) {
    __shared__ int   scol[RWARPS][ELLW];
    __shared__ float sval[RWARPS][ELLW];
    __shared__ float sw[RWARPS][ELLW];

    const int wr   = threadIdx.x >> 5;
    const int lane = threadIdx.x & 31;
    const int row  = blockIdx.x * RWARPS + wr;
    if (row >= N_NODES) return;

    int k = g_cnt[row];
    if (k > ELLW) k = ELLW;
    const int* ecol = g_ecol + row * ELLW;

    float* op = out + (size_t)row * OUT_F + lane * 8;
    if (k == 0) {
        // all-NEG_BIG row: uniform softmax -> column mean (prob ~e^-32; inline)
        float4 a0 = make_float4(0.f, 0.f, 0.f, 0.f);
        float4 a1 = make_float4(0.f, 0.f, 0.f, 0.f);
        for (int r = 0; r < N_NODES; r++) {
            uint4 hv = *(const uint4*)(g_h16 + (size_t)r * OUT_F + lane * 8);
            float2 f0 = __half22float2(*(__half2*)&hv.x);
            float2 f1 = __half22float2(*(__half2*)&hv.y);
            float2 f2 = __half22float2(*(__half2*)&hv.z);
            float2 f3 = __half22float2(*(__half2*)&hv.w);
            a0.x += f0.x; a0.y += f0.y; a0.z += f1.x; a0.w += f1.y;
            a1.x += f2.x; a1.y += f2.y; a1.z += f3.x; a1.w += f3.y;
        }
        const float s = 1.0f / N_NODES;
        *(float4*)op       = make_float4(a0.x * s, a0.y * s, a0.z * s, a0.w * s);
        *(float4*)(op + 4) = make_float4(a1.x * s, a1.y * s, a1.z * s, a1.w * s);
        return;
    }

    int*   cols = scol[wr];
    float* val  = sval[wr];
    float* wt   = sw[wr];

    const float s1 = g_s1[row];
    for (int t = lane; t < k; t += 32) {
        int c = ecol[t];
        cols[t] = c;
        float sc = s1 + g_s2[c];
        val[t] = sc > 0.f ? sc : ALPHA * sc;   // leaky per edge BEFORE scatter-add
    }
    __syncwarp();

    // dedup: first occurrence owns and sums duplicates (scatter-add semantics)
    for (int t = lane; t < k; t += 32) {
        int c = cols[t];
        bool owner = true;
        for (int j = 0; j < t; j++)
            if (cols[j] == c) { owner = false; break; }
        float v;
        if (owner) {
            v = val[t];
            for (int j = t + 1; j < k; j++)
                if (cols[j] == c) v += val[j];
        } else {
            v = -CUDART_INF_F;
        }
        wt[t] = v;
    }
    __syncwarp();

    float m = -CUDART_INF_F;
    for (int t = lane; t < k; t += 32) m = fmaxf(m, wt[t]);
#pragma unroll
    for (int o = 16; o; o >>= 1) m = fmaxf(m, __shfl_xor_sync(0xffffffffu, m, o));

    float z = 0.f;
    for (int t = lane; t < k; t += 32) {
        float e = __expf(wt[t] - m);
        wt[t] = e;
        z += e;
    }
#pragma unroll
    for (int o = 16; o; o >>= 1) z += __shfl_xor_sync(0xffffffffu, z, o);
    float invZ = 1.0f / z;
    __syncwarp();

    // aggregation: lane owns 8 cols; one uint4 (8 halves) load per edge
    float4 a0 = make_float4(0.f, 0.f, 0.f, 0.f);
    float4 a1 = make_float4(0.f, 0.f, 0.f, 0.f);
#pragma unroll 4
    for (int t = 0; t < k; t++) {
        float wv = wt[t];
        uint4 hv = *(const uint4*)(g_h16 + (size_t)cols[t] * OUT_F + lane * 8);
        float2 f0 = __half22float2(*(__half2*)&hv.x);
        float2 f1 = __half22float2(*(__half2*)&hv.y);
        float2 f2 = __half22float2(*(__half2*)&hv.z);
        float2 f3 = __half22float2(*(__half2*)&hv.w);
        a0.x += wv * f0.x; a0.y += wv * f0.y; a0.z += wv * f1.x; a0.w += wv * f1.y;
        a1.x += wv * f2.x; a1.y += wv * f2.y; a1.z += wv * f3.x; a1.w += wv * f3.y;
    }
    *(float4*)op       = make_float4(a0.x * invZ, a0.y * invZ, a0.z * invZ, a0.w * invZ);
    *(float4*)(op + 4) = make_float4(a1.x * invZ, a1.y * invZ, a1.z * invZ, a1.w * invZ);
}

// ---------------- launch ---------------------------------------------------
extern "C" void kernel_launch(void* const* d_in, const int* in_sizes, int n_in,
                              void* d_out, int out_size) {
    const float* x  = (const float*)d_in[0];
    const float* W  = (const float*)d_in[1];
    const float* b  = (const float*)d_in[2];
    const float* a  = (const float*)d_in[3];
    const void*  el = d_in[4];
    float* out = (float*)d_out;

    static cudaStream_t s_side = nullptr;
    static cudaEvent_t  ev_fork = nullptr, ev_setup = nullptr, ev_side = nullptr;
    static bool s_init = false;
    if (!s_init) {
        cudaStreamCreateWithFlags(&s_side, cudaStreamNonBlocking);
        cudaEventCreateWithFlags(&ev_fork, cudaEventDisableTiming);
        cudaEventCreateWithFlags(&ev_setup, cudaEventDisableTiming);
        cudaEventCreateWithFlags(&ev_side, cudaEventDisableTiming);
        cudaFuncSetAttribute(gemm_mma_kernel,
                             cudaFuncAttributeMaxDynamicSharedMemorySize, SM_GEMM);
        s_init = true;
    }

    cudaEventRecord(ev_fork, 0);
    cudaStreamWaitEvent(s_side, ev_fork, 0);

    // side: setup (wcvt + init fused) -> count (direct ELL scatter)
    int setup_blocks = WCVT_BLOCKS + (N_NODES + 255) / 256;
    setup_kernel<<<setup_blocks, 256, 0, s_side>>>(W, (const int*)el);
    cudaEventRecord(ev_setup, s_side);   // g_w16 ready, s1/s2/cnt zeroed
    count_kernel<<<(N_EDGES / 4 + 255) / 256, 256, 0, s_side>>>(el);
    cudaEventRecord(ev_side, s_side);

    // main: gemm (fused X conversion; needs setup) -> row (needs everything)
    cudaStreamWaitEvent(0, ev_setup, 0);
    dim3 ggrid((N_NODES + BM - 1) / BM, OUT_F / BN);
    gemm_mma_kernel<<<ggrid, 256, SM_GEMM>>>(x, b, a);

    cudaStreamWaitEvent(0, ev_side, 0);
    row_kernel<<<(N_NODES + RWARPS - 1) / RWARPS, 32 * RWARPS>>>(out);
}

// round 17
// speedup vs baseline: 1.7660x; 1.7149x over previous
#include <cuda_runtime.h>
#include <cuda_fp16.h>
#include <math_constants.h>
#include <cstdint>
#include <cstring>

#define N_NODES 10000
#define N_EDGES 320000
#define IN_F    512
#define OUT_F   256
#define ALPHA   0.2f
#define ELLW    96          // ELL row capacity (P(Poisson(32) > 96) < 1e-18)

// ---------------- scratch (device globals; no allocation allowed) ----------
__device__ __half g_h16[(size_t)N_NODES * OUT_F];
__device__ float g_s1[N_NODES];
__device__ float g_s2[N_NODES];
__device__ int   g_cnt[N_NODES];
__device__ int   g_ecol[(size_t)N_NODES * ELLW];
__device__ int   g_is64;
__device__ __half g_w16[(size_t)OUT_F * IN_F];

// ---------------- small helpers --------------------------------------------
__device__ __forceinline__ uint32_t h2_bits(__half2 h) {
    uint32_t u;
    memcpy(&u, &h, 4);
    return u;
}
__device__ __forceinline__ void ldsm4(uint32_t* r, uint32_t addr) {
    asm volatile("ldmatrix.sync.aligned.m8n8.x4.shared.b16 {%0,%1,%2,%3}, [%4];"
                 : "=r"(r[0]), "=r"(r[1]), "=r"(r[2]), "=r"(r[3]) : "r"(addr));
}
__device__ __forceinline__ void mma16816(float* c, const uint32_t* A, uint32_t b0, uint32_t b1) {
    asm volatile("mma.sync.aligned.m16n8k16.row.col.f32.f16.f16.f32 "
                 "{%0,%1,%2,%3}, {%4,%5,%6,%7}, {%8,%9}, {%0,%1,%2,%3};"
                 : "+f"(c[0]), "+f"(c[1]), "+f"(c[2]), "+f"(c[3])
                 : "r"(A[0]), "r"(A[1]), "r"(A[2]), "r"(A[3]), "r"(b0), "r"(b1));
}
__device__ __forceinline__ void cpa16(uint32_t dst, const void* src) {
    asm volatile("cp.async.cg.shared.global [%0], [%1], 16;" :: "r"(dst), "l"(src));
}
__device__ __forceinline__ int clampN(int v) {
    return (v < 0) ? 0 : (v >= N_NODES ? N_NODES - 1 : v);
}

// ---------------- setup: W fp32->fp16 (blocks 0..63) + init (blocks 64..) ---
#define WCVT_BLOCKS 64   // 64 * 256 threads * 8 floats = 131072 = OUT_F*IN_F
__global__ void setup_kernel(const float* __restrict__ W, const int* __restrict__ p) {
    if (blockIdx.x < WCVT_BLOCKS) {
        int i = blockIdx.x * blockDim.x + threadIdx.x;   // 8 floats per thread
        float4 v0 = ((const float4*)W)[2 * i];
        float4 v1 = ((const float4*)W)[2 * i + 1];
        __half2 H0 = {__float2half_rn(v0.x), __float2half_rn(v0.y)};
        __half2 H1 = {__float2half_rn(v0.z), __float2half_rn(v0.w)};
        __half2 H2 = {__float2half_rn(v1.x), __float2half_rn(v1.y)};
        __half2 H3 = {__float2half_rn(v1.z), __float2half_rn(v1.w)};
        ((__half2*)g_w16)[4 * i]     = H0;
        ((__half2*)g_w16)[4 * i + 1] = H1;
        ((__half2*)g_w16)[4 * i + 2] = H2;
        ((__half2*)g_w16)[4 * i + 3] = H3;
    } else {
        int i = (blockIdx.x - WCVT_BLOCKS) * blockDim.x + threadIdx.x;
        if (i == 0) {
            int nz = 0;
#pragma unroll
            for (int j = 0; j < 64; j++) nz |= p[2 * j + 1];
            g_is64 = (nz == 0) ? 1 : 0;
        }
        if (i < N_NODES) { g_cnt[i] = 0; g_s1[i] = 0.f; g_s2[i] = 0.f; }
    }
}

// ---------------- count: direct ELL scatter (no scan, no fill) --------------
__global__ void count_kernel(const void* __restrict__ el) {
    int e0 = (blockIdx.x * blockDim.x + threadIdx.x) * 4;
    if (e0 >= N_EDGES) return;
    int s[4], t[4];
    if (g_is64) {
        const longlong2* sp = (const longlong2*)el;
        const longlong2* tp = (const longlong2*)((const long long*)el + N_EDGES);
        longlong2 s0 = sp[e0 >> 1], s1 = sp[(e0 >> 1) + 1];
        longlong2 t0 = tp[e0 >> 1], t1 = tp[(e0 >> 1) + 1];
        s[0] = clampN((int)s0.x); s[1] = clampN((int)s0.y);
        s[2] = clampN((int)s1.x); s[3] = clampN((int)s1.y);
        t[0] = clampN((int)t0.x); t[1] = clampN((int)t0.y);
        t[2] = clampN((int)t1.x); t[3] = clampN((int)t1.y);
    } else {
        int4 sv = ((const int4*)el)[e0 >> 2];
        int4 tv = ((const int4*)((const int*)el + N_EDGES))[e0 >> 2];
        s[0] = clampN(sv.x); s[1] = clampN(sv.y); s[2] = clampN(sv.z); s[3] = clampN(sv.w);
        t[0] = clampN(tv.x); t[1] = clampN(tv.y); t[2] = clampN(tv.z); t[3] = clampN(tv.w);
    }
#pragma unroll
    for (int u = 0; u < 4; u++) {
        int rank = atomicAdd(&g_cnt[s[u]], 1);
        if (rank < ELLW) g_ecol[s[u] * ELLW + rank] = t[u];
    }
}

// ---------------- tensor-core GEMM, fused X fp32->fp16, reg-pipelined ------
#define BM 128
#define BN 128
#define KB 32
#define KST 40
#define STG_B (BM * KST * 2)        // 10240 bytes per stage per array
#define NC (IN_F / KB)              // 16
#define SM_GEMM (4 * STG_B)         // A0,A1,B0,B1 = 40960

__global__ void __launch_bounds__(256, 2) gemm_mma_kernel(
    const float* __restrict__ X,
    const float* __restrict__ bias, const float* __restrict__ av)
{
    extern __shared__ char dsm[];
    const uint32_t smb = (uint32_t)__cvta_generic_to_shared(dsm);

    const int tid  = threadIdx.x;
    const int lane = tid & 31;
    const int wid  = tid >> 5;
    const int wm   = wid & 3;
    const int wn   = wid >> 2;
    const int bm   = blockIdx.x * BM;
    const int bn   = blockIdx.y * BN;

    float acc[2][8][4];
#pragma unroll
    for (int i = 0; i < 2; i++)
#pragma unroll
        for (int j = 0; j < 8; j++)
#pragma unroll
            for (int q = 0; q < 4; q++) acc[i][j][q] = 0.f;

    const int sr = tid >> 1;
    const int sh = (tid & 1) * 16;
    const int rowA = (bm + sr < N_NODES) ? bm + sr : N_NODES - 1;
    const float*  xp = X + (size_t)rowA * IN_F + sh;
    const __half* wp = g_w16 + (size_t)(bn + sr) * IN_F + sh;
    const uint32_t sdst = (uint32_t)(sr * KST + sh) * 2;

    const uint32_t a_row = lane & 15, a_cb = (lane >> 4) * 8;
    const uint32_t b_row = (lane & 7) + ((lane & 16) ? 8 : 0);
    const uint32_t b_cb  = (lane & 8) ? 8 : 0;

    uint32_t xr[8];
#define LOADX(ch) do {                                            \
    const float* _p = xp + (ch) * KB;                             \
    float4 v0 = *(const float4*)(_p);                             \
    float4 v1 = *(const float4*)(_p + 4);                         \
    float4 v2 = *(const float4*)(_p + 8);                         \
    float4 v3 = *(const float4*)(_p + 12);                        \
    xr[0] = h2_bits(__floats2half2_rn(v0.x, v0.y));               \
    xr[1] = h2_bits(__floats2half2_rn(v0.z, v0.w));               \
    xr[2] = h2_bits(__floats2half2_rn(v1.x, v1.y));               \
    xr[3] = h2_bits(__floats2half2_rn(v1.z, v1.w));               \
    xr[4] = h2_bits(__floats2half2_rn(v2.x, v2.y));               \
    xr[5] = h2_bits(__floats2half2_rn(v2.z, v2.w));               \
    xr[6] = h2_bits(__floats2half2_rn(v3.x, v3.y));               \
    xr[7] = h2_bits(__floats2half2_rn(v3.z, v3.w));               \
} while (0)

#define CPW(ch) do {                                              \
    uint32_t _b = smb + 2 * STG_B + ((ch) & 1) * STG_B + sdst;    \
    cpa16(_b,      wp + (ch) * KB);                               \
    cpa16(_b + 16, wp + (ch) * KB + 8);                           \
    asm volatile("cp.async.commit_group;" ::: "memory");          \
} while (0)

    LOADX(0);
    CPW(0);

    for (int ch = 0; ch < NC; ch++) {
        __syncthreads();
        {
            uint32_t _a = smb + (ch & 1) * STG_B + sdst;
            asm volatile("st.shared.v4.b32 [%0], {%1,%2,%3,%4};"
                         :: "r"(_a), "r"(xr[0]), "r"(xr[1]), "r"(xr[2]), "r"(xr[3]));
            asm volatile("st.shared.v4.b32 [%0], {%1,%2,%3,%4};"
                         :: "r"(_a + 16), "r"(xr[4]), "r"(xr[5]), "r"(xr[6]), "r"(xr[7]));
        }
        if (ch + 1 < NC) {
            CPW(ch + 1);
            LOADX(ch + 1);
            asm volatile("cp.async.wait_group 1;" ::: "memory");
        } else {
            asm volatile("cp.async.wait_group 0;" ::: "memory");
        }
        __syncthreads();

        const uint32_t sA_b = smb + (ch & 1) * STG_B;
        const uint32_t sB_b = smb + 2 * STG_B + (ch & 1) * STG_B;

#pragma unroll
        for (int ks = 0; ks < KB; ks += 16) {
            uint32_t ah[2][4];
#pragma unroll
            for (int mi = 0; mi < 2; mi++) {
                uint32_t off = ((wm * 32 + mi * 16 + a_row) * KST + ks + a_cb) * 2;
                ldsm4(ah[mi], sA_b + off);
            }
#pragma unroll
            for (int g = 0; g < 4; g++) {
                uint32_t off = ((wn * 64 + g * 16 + b_row) * KST + ks + b_cb) * 2;
                uint32_t bh[4];
                ldsm4(bh, sB_b + off);
#pragma unroll
                for (int mi = 0; mi < 2; mi++) {
                    mma16816(acc[mi][2 * g],     ah[mi], bh[0], bh[1]);
                    mma16816(acc[mi][2 * g + 1], ah[mi], bh[2], bh[3]);
                }
            }
        }
    }
#undef LOADX
#undef CPW

    const int q  = lane >> 2;
    const int qt = lane & 3;
#pragma unroll
    for (int mi = 0; mi < 2; mi++) {
#pragma unroll
        for (int half = 0; half < 2; half++) {
            int row = bm + wm * 32 + mi * 16 + half * 8 + q;
            bool vr = (row < N_NODES);
            float p1 = 0.f, p2 = 0.f;
#pragma unroll
            for (int ni = 0; ni < 8; ni++) {
                int col = bn + wn * 64 + ni * 8 + qt * 2;
                float v0 = acc[mi][ni][half * 2 + 0] + bias[col];
                float v1 = acc[mi][ni][half * 2 + 1] + bias[col + 1];
                if (vr) {
                    __half2 hh = __floats2half2_rn(v0, v1);
                    *(__half2*)(g_h16 + (size_t)row * OUT_F + col) = hh;
                }
                p1 += v0 * av[col]         + v1 * av[col + 1];
                p2 += v0 * av[OUT_F + col] + v1 * av[OUT_F + col + 1];
            }
            p1 += __shfl_xor_sync(0xffffffffu, p1, 1);
            p1 += __shfl_xor_sync(0xffffffffu, p1, 2);
            p2 += __shfl_xor_sync(0xffffffffu, p2, 1);
            p2 += __shfl_xor_sync(0xffffffffu, p2, 2);
            if (qt == 0 && vr) {
                atomicAdd(&g_s1[row], p1);
                atomicAdd(&g_s2[row], p2);
            }
        }
    }
}

// ---------------- per-row: warp-per-row dedup + softmax + aggregation ------
#define RWARPS 4

__global__ void __launch_bounds__(32 * RWARPS) row_kernel(float* __restrict__ out) {
    __shared__ int   scol[RWARPS][ELLW];
    __shared__ float sval[RWARPS][ELLW];
    __shared__ float sw[RWARPS][ELLW];

    const int wr   = threadIdx.x >> 5;
    const int lane = threadIdx.x & 31;
    const int row  = blockIdx.x * RWARPS + wr;
    if (row >= N_NODES) return;

    int k = g_cnt[row];
    if (k > ELLW) k = ELLW;
    const int* ecol = g_ecol + row * ELLW;

    float* op = out + (size_t)row * OUT_F + lane * 8;
    if (k == 0) {
        // all-NEG_BIG row: uniform softmax -> column mean (prob ~e^-32; inline)
        float4 a0 = make_float4(0.f, 0.f, 0.f, 0.f);
        float4 a1 = make_float4(0.f, 0.f, 0.f, 0.f);
        for (int r = 0; r < N_NODES; r++) {
            uint4 hv = *(const uint4*)(g_h16 + (size_t)r * OUT_F + lane * 8);
            float2 f0 = __half22float2(*(__half2*)&hv.x);
            float2 f1 = __half22float2(*(__half2*)&hv.y);
            float2 f2 = __half22float2(*(__half2*)&hv.z);
            float2 f3 = __half22float2(*(__half2*)&hv.w);
            a0.x += f0.x; a0.y += f0.y; a0.z += f1.x; a0.w += f1.y;
            a1.x += f2.x; a1.y += f2.y; a1.z += f3.x; a1.w += f3.y;
        }
        const float s = 1.0f / N_NODES;
        *(float4*)op       = make_float4(a0.x * s, a0.y * s, a0.z * s, a0.w * s);
        *(float4*)(op + 4) = make_float4(a1.x * s, a1.y * s, a1.z * s, a1.w * s);
        return;
    }

    int*   cols = scol[wr];
    float* val  = sval[wr];
    float* wt   = sw[wr];

    const float s1 = g_s1[row];
    for (int t = lane; t < k; t += 32) {
        int c = ecol[t];
        cols[t] = c;
        float sc = s1 + g_s2[c];
        val[t] = sc > 0.f ? sc : ALPHA * sc;   // leaky per edge BEFORE scatter-add
    }
    __syncwarp();

    // ---- dedup (scatter-add semantics: sum duplicate leaky scores) ----
    // Fast path: k<=32 AND no duplicate tgt in this row (>95% of such rows):
    // one match_any + ballot replaces the O(k^2) smem pass entirely.
    bool fast = false;
    if (k <= 32) {
        int c = (lane < k) ? cols[lane] : (-2 - lane);   // unique sentinels
        unsigned mask = __match_any_sync(0xffffffffu, c);
        fast = __all_sync(0xffffffffu, __popc(mask) == 1);
        if (fast && lane < k) wt[lane] = val[lane];
    }
    if (!fast) {
        // branchless predicated pass: independent LDS, pipelineable
        for (int t = lane; t < k; t += 32) {
            int c = cols[t];
            float v = val[t];
            bool owner = true;
#pragma unroll 4
            for (int j = 0; j < k; j++) {
                bool m = (cols[j] == c);
                owner = owner && !(m && (j < t));
                v += (m && (j > t)) ? val[j] : 0.f;
            }
            wt[t] = owner ? v : -CUDART_INF_F;
        }
    }
    __syncwarp();

    float m = -CUDART_INF_F;
    for (int t = lane; t < k; t += 32) m = fmaxf(m, wt[t]);
#pragma unroll
    for (int o = 16; o; o >>= 1) m = fmaxf(m, __shfl_xor_sync(0xffffffffu, m, o));

    float z = 0.f;
    for (int t = lane; t < k; t += 32) {
        float e = __expf(wt[t] - m);
        wt[t] = e;
        z += e;
    }
#pragma unroll
    for (int o = 16; o; o >>= 1) z += __shfl_xor_sync(0xffffffffu, z, o);
    float invZ = 1.0f / z;
    __syncwarp();

    // aggregation: lane owns 8 cols; one uint4 (8 halves) load per edge
    float4 a0 = make_float4(0.f, 0.f, 0.f, 0.f);
    float4 a1 = make_float4(0.f, 0.f, 0.f, 0.f);
#pragma unroll 4
    for (int t = 0; t < k; t++) {
        float wv = wt[t];
        uint4 hv = *(const uint4*)(g_h16 + (size_t)cols[t] * OUT_F + lane * 8);
        float2 f0 = __half22float2(*(__half2*)&hv.x);
        float2 f1 = __half22float2(*(__half2*)&hv.y);
        float2 f2 = __half22float2(*(__half2*)&hv.z);
        float2 f3 = __half22float2(*(__half2*)&hv.w);
        a0.x += wv * f0.x; a0.y += wv * f0.y; a0.z += wv * f1.x; a0.w += wv * f1.y;
        a1.x += wv * f2.x; a1.y += wv * f2.y; a1.z += wv * f3.x; a1.w += wv * f3.y;
    }
    *(float4*)op       = make_float4(a0.x * invZ, a0.y * invZ, a0.z * invZ, a0.w * invZ);
    *(float4*)(op + 4) = make_float4(a1.x * invZ, a1.y * invZ, a1.z * invZ, a1.w * invZ);
}

// ---------------- launch ---------------------------------------------------
extern "C" void kernel_launch(void* const* d_in, const int* in_sizes, int n_in,
                              void* d_out, int out_size) {
    const float* x  = (const float*)d_in[0];
    const float* W  = (const float*)d_in[1];
    const float* b  = (const float*)d_in[2];
    const float* a  = (const float*)d_in[3];
    const void*  el = d_in[4];
    float* out = (float*)d_out;

    static cudaStream_t s_side = nullptr;
    static cudaEvent_t  ev_fork = nullptr, ev_setup = nullptr, ev_side = nullptr;
    static bool s_init = false;
    if (!s_init) {
        cudaStreamCreateWithFlags(&s_side, cudaStreamNonBlocking);
        cudaEventCreateWithFlags(&ev_fork, cudaEventDisableTiming);
        cudaEventCreateWithFlags(&ev_setup, cudaEventDisableTiming);
        cudaEventCreateWithFlags(&ev_side, cudaEventDisableTiming);
        cudaFuncSetAttribute(gemm_mma_kernel,
                             cudaFuncAttributeMaxDynamicSharedMemorySize, SM_GEMM);
        s_init = true;
    }

    cudaEventRecord(ev_fork, 0);
    cudaStreamWaitEvent(s_side, ev_fork, 0);

    // side: setup (wcvt + init fused) -> count (direct ELL scatter)
    int setup_blocks = WCVT_BLOCKS + (N_NODES + 255) / 256;
    setup_kernel<<<setup_blocks, 256, 0, s_side>>>(W, (const int*)el);
    cudaEventRecord(ev_setup, s_side);   // g_w16 ready, s1/s2/cnt zeroed
    count_kernel<<<(N_EDGES / 4 + 255) / 256, 256, 0, s_side>>>(el);
    cudaEventRecord(ev_side, s_side);

    // main: gemm (fused X conversion; needs setup) -> row (needs everything)
    cudaStreamWaitEvent(0, ev_setup, 0);
    dim3 ggrid((N_NODES + BM - 1) / BM, OUT_F / BN);
    gemm_mma_kernel<<<ggrid, 256, SM_GEMM>>>(x, b, a);

    cudaStreamWaitEvent(0, ev_side, 0);
    row_kernel<<<(N_NODES + RWARPS - 1) / RWARPS, 32 * RWARPS>>>(out);
}